// round 7
// baseline (speedup 1.0000x reference)
#include <cuda_runtime.h>
#include <cuda_bf16.h>
#include <math.h>
#include <stdint.h>

#define BATCH 2
#define SEQ   2048
#define DMODEL 4096
#define NHEADS 32
#define NKVH  8
#define HEADD 128
#define KVLEN 2048

#define QSCALE 0.08838834764831845f

// ---------------------------------------------------------------------------
// Global scratch: bf16 hi/lo planes stored as packed bf16x2 (uint32).
// ---------------------------------------------------------------------------
#define PLANE_U32 (8388608)
__device__ uint32_t g_xhi[PLANE_U32],  g_xlo[PLANE_U32];   // x rows (b*s, k)
__device__ uint32_t g_wqhi[PLANE_U32], g_wqlo[PLANE_U32];  // wq (n, k)
__device__ uint32_t g_wohi[PLANE_U32], g_wolo[PLANE_U32];  // wo (n, k)
__device__ uint32_t g_qhi[PLANE_U32],  g_qlo[PLANE_U32];   // q (b,h,s,d)
__device__ uint32_t g_ahi[PLANE_U32],  g_alo[PLANE_U32];   // attn out (b*s, h*d)
#define KV_U32 (2097152)
__device__ uint32_t g_khi[KV_U32], g_klo[KV_U32];          // (b,g,s,d)
__device__ uint32_t g_vhi[KV_U32], g_vlo[KV_U32];

// ---------------------------------------------------------------------------
__device__ __forceinline__ uint32_t smem_to_u32(const void* p) {
    uint32_t a;
    asm("{ .reg .u64 t; cvta.to.shared.u64 t, %1; cvt.u32.u64 %0, t; }" : "=r"(a) : "l"(p));
    return a;
}
#define SWZ128(off) ((uint32_t)(off) ^ ((((uint32_t)(off)) >> 3) & 0x70u))
#define SWZ256(off) ((uint32_t)(off) ^ ((((uint32_t)(off)) >> 4) & 0x70u))

__device__ __forceinline__ void cp16(uint32_t dst, const void* src) {
    asm volatile("cp.async.cg.shared.global [%0], [%1], 16;" :: "r"(dst), "l"(src));
}
#define CP_COMMIT asm volatile("cp.async.commit_group;" ::: "memory")
#define CP_WAIT(n) asm volatile("cp.async.wait_group %0;" :: "n"(n) : "memory")

__device__ __forceinline__ void ldsm_x4(uint32_t& r0, uint32_t& r1, uint32_t& r2, uint32_t& r3,
                                        uint32_t addr) {
    asm volatile("ldmatrix.sync.aligned.m8n8.x4.shared.b16 {%0,%1,%2,%3}, [%4];"
                 : "=r"(r0), "=r"(r1), "=r"(r2), "=r"(r3) : "r"(addr));
}
__device__ __forceinline__ void ldsm_x4_t(uint32_t& r0, uint32_t& r1, uint32_t& r2, uint32_t& r3,
                                          uint32_t addr) {
    asm volatile("ldmatrix.sync.aligned.m8n8.x4.trans.shared.b16 {%0,%1,%2,%3}, [%4];"
                 : "=r"(r0), "=r"(r1), "=r"(r2), "=r"(r3) : "r"(addr));
}
__device__ __forceinline__ void mma_bf16(float* d, const uint32_t* a, uint32_t b0, uint32_t b1) {
    asm volatile(
        "mma.sync.aligned.m16n8k16.row.col.f32.bf16.bf16.f32 "
        "{%0,%1,%2,%3}, {%4,%5,%6,%7}, {%8,%9}, {%0,%1,%2,%3};"
        : "+f"(d[0]), "+f"(d[1]), "+f"(d[2]), "+f"(d[3])
        : "r"(a[0]), "r"(a[1]), "r"(a[2]), "r"(a[3]), "r"(b0), "r"(b1));
}
__device__ __forceinline__ void pack_hilo(float a, float b, uint32_t& hi, uint32_t& lo) {
    uint32_t h;
    asm("cvt.rn.bf16x2.f32 %0, %1, %2;" : "=r"(h) : "f"(b), "f"(a));
    float fa = __uint_as_float(h << 16);
    float fb = __uint_as_float(h & 0xffff0000u);
    float ra = a - fa;
    float rb = b - fb;
    uint32_t l;
    asm("cvt.rn.bf16x2.f32 %0, %1, %2;" : "=r"(l) : "f"(rb), "f"(ra));
    hi = h; lo = l;
}

// ---------------------------------------------------------------------------
// Fused conversion kernels (float4-wide)
// ---------------------------------------------------------------------------
__global__ void conv3(const float4* __restrict__ s0, const float4* __restrict__ s1,
                      const float4* __restrict__ s2,
                      uint2* h0, uint2* l0, uint2* h1, uint2* l1, uint2* h2, uint2* l2)
{
    const float4* src = (blockIdx.y == 0) ? s0 : (blockIdx.y == 1) ? s1 : s2;
    uint2* hi = (blockIdx.y == 0) ? h0 : (blockIdx.y == 1) ? h1 : h2;
    uint2* lo = (blockIdx.y == 0) ? l0 : (blockIdx.y == 1) ? l1 : l2;
    const int n4 = PLANE_U32 / 2;
    for (int i = blockIdx.x * blockDim.x + threadIdx.x; i < n4;
         i += gridDim.x * blockDim.x) {
        float4 v = src[i];
        uint32_t ha, la, hb, lb;
        pack_hilo(v.x, v.y, ha, la);
        pack_hilo(v.z, v.w, hb, lb);
        hi[i] = make_uint2(ha, hb);
        lo[i] = make_uint2(la, lb);
    }
}

// cache (b,s,g,d) fp32 -> planes (b,g,s,d)
__global__ void conv_kv4(const float4* __restrict__ ksrc, const float4* __restrict__ vsrc,
                         uint2* kh, uint2* kl, uint2* vh, uint2* vl)
{
    const float4* src = blockIdx.y ? vsrc : ksrc;
    uint2* hi = blockIdx.y ? vh : kh;
    uint2* lo = blockIdx.y ? vl : kl;
    const int n4 = KV_U32 / 2;
    for (int p = blockIdx.x * blockDim.x + threadIdx.x; p < n4;
         p += gridDim.x * blockDim.x) {
        const int d4 = p & 31;
        const int s = (p >> 5) & 2047;
        const int g = (p >> 16) & 7;
        const int b = p >> 19;
        float4 v = src[(((size_t)b * SEQ + s) * NKVH + g) * 32 + d4];
        uint32_t ha, la, hb, lb;
        pack_hilo(v.x, v.y, ha, la);
        pack_hilo(v.z, v.w, hb, lb);
        hi[p] = make_uint2(ha, hb);
        lo[p] = make_uint2(la, lb);
    }
}

// ---------------------------------------------------------------------------
// Pipelined bf16-split GEMM: C[M,N] = A[M,K] @ B[N,K]^T  (4096^3)
// 3 passes: Ahi*Bhi + Ahi*Blo + Alo*Bhi. CTA 128x256, 8 warps (64x64 each),
// K-chunk 64, 2-stage cp.async (96KB stages).
// Stage layout: Ahi[16K] Alo[16K] Bhi[32K] Blo[32K].
// EPI=0: fp32 store to C.  EPI=1: Q-proj (freqs*QSCALE, bf16 hi/lo -> Qh/Ql).
// ---------------------------------------------------------------------------
#define GEMM_SMEM (2 * 98304)

template <int EPI>
__global__ __launch_bounds__(256, 1) void gemm_bf16(
    const uint32_t* __restrict__ Ahi, const uint32_t* __restrict__ Alo,
    const uint32_t* __restrict__ Bhi, const uint32_t* __restrict__ Blo,
    float* __restrict__ C, const float* __restrict__ freqs,
    uint32_t* __restrict__ Qh, uint32_t* __restrict__ Ql)
{
    extern __shared__ char sm[];
    const uint32_t smb = smem_to_u32(sm);
    const int tid = threadIdx.x;
    const int wid = tid >> 5;
    const int lane = tid & 31;
    const int wm = wid & 1;          // m half (64)
    const int wn = wid >> 1;         // n quarter (64)
    const int m0 = blockIdx.y * 128;
    const int n0 = blockIdx.x * 256;

    float acc[4][8][4];
#pragma unroll
    for (int i = 0; i < 4; i++)
#pragma unroll
        for (int j = 0; j < 8; j++)
#pragma unroll
            for (int v = 0; v < 4; v++) acc[i][j][v] = 0.0f;

    auto load_stage = [&](int ch, int st) {
        const uint32_t sbase = smb + st * 98304u;
        const int kc2 = ch * 32;
#pragma unroll
        for (int t = tid; t < 6144; t += 256) {
            if (t < 2048) {
                const int plane = t >> 10;
                const int i = t & 1023;
                const int row = i >> 3, ck = i & 7;
                const uint32_t dst = sbase + plane * 16384u + SWZ128(row * 128 + ck * 16);
                cp16(dst, (plane ? Alo : Ahi) + (size_t)(m0 + row) * 2048 + kc2 + ck * 4);
            } else {
                const int u = t - 2048;
                const int plane = u >> 11;
                const int i = u & 2047;
                const int row = i >> 3, ck = i & 7;
                const uint32_t dst = sbase + 32768u + plane * 32768u + SWZ128(row * 128 + ck * 16);
                cp16(dst, (plane ? Blo : Bhi) + (size_t)(n0 + row) * 2048 + kc2 + ck * 4);
            }
        }
    };

    const int q = lane >> 3;
    const int wi = lane & 7;
    const int arow_base = wm * 64 + wi + ((q & 1) ? 8 : 0);
    const int akb_off = (q & 2) ? 16 : 0;
    const int brow_base = wn * 64 + wi + ((q & 2) ? 8 : 0);
    const int bkb_off = (q & 1) ? 16 : 0;

    load_stage(0, 0); CP_COMMIT;

    for (int ch = 0; ch < 64; ++ch) {
        CP_WAIT(0);
        __syncthreads();   // all warps done reading the stage about to be refilled
        if (ch + 1 < 64) { load_stage(ch + 1, (ch + 1) & 1); CP_COMMIT; }

        const uint32_t sbase = smb + (uint32_t)(ch & 1) * 98304u;
        const uint32_t pAhi = sbase, pAlo = sbase + 16384u;
        const uint32_t pBhi = sbase + 32768u, pBlo = sbase + 65536u;

#pragma unroll
        for (int ks = 0; ks < 4; ++ks) {
            const int kb0 = ks * 32;
            uint32_t ah[4][4], al[4][4];
#pragma unroll
            for (int mt = 0; mt < 4; ++mt) {
                const int r = arow_base + mt * 16;
                const uint32_t off = SWZ128(r * 128 + kb0 + akb_off);
                ldsm_x4(ah[mt][0], ah[mt][1], ah[mt][2], ah[mt][3], pAhi + off);
                ldsm_x4(al[mt][0], al[mt][1], al[mt][2], al[mt][3], pAlo + off);
            }
#pragma unroll
            for (int np = 0; np < 4; ++np) {
                const int rn = brow_base + np * 16;
                const uint32_t offb = SWZ128(rn * 128 + kb0 + bkb_off);
                uint32_t bh[4], bl[4];
                ldsm_x4(bh[0], bh[1], bh[2], bh[3], pBhi + offb);
                ldsm_x4(bl[0], bl[1], bl[2], bl[3], pBlo + offb);
#pragma unroll
                for (int mt = 0; mt < 4; ++mt) {
                    mma_bf16(acc[mt][np * 2],     ah[mt], bh[0], bh[1]);
                    mma_bf16(acc[mt][np * 2 + 1], ah[mt], bh[2], bh[3]);
                    mma_bf16(acc[mt][np * 2],     ah[mt], bl[0], bl[1]);
                    mma_bf16(acc[mt][np * 2 + 1], ah[mt], bl[2], bl[3]);
                    mma_bf16(acc[mt][np * 2],     al[mt], bh[0], bh[1]);
                    mma_bf16(acc[mt][np * 2 + 1], al[mt], bh[2], bh[3]);
                }
            }
        }
    }

    // epilogue from registers
    const int rl = lane >> 2;
    const int cl = (lane & 3) * 2;
#pragma unroll
    for (int mt = 0; mt < 4; ++mt) {
#pragma unroll
        for (int nn = 0; nn < 8; ++nn) {
            const int r = m0 + wm * 64 + mt * 16 + rl;
            const int c = n0 + wn * 64 + nn * 8 + cl;
#pragma unroll
            for (int half = 0; half < 2; ++half) {
                const int rr = r + half * 8;
                const float v0 = acc[mt][nn][half * 2];
                const float v1 = acc[mt][nn][half * 2 + 1];
                if (EPI == 0) {
                    *(float2*)&C[(size_t)rr * DMODEL + c] = make_float2(v0, v1);
                } else {
                    const int b = rr >> 11;
                    const int s = rr & (SEQ - 1);
                    const int h = c >> 7;
                    const int d = c & (HEADD - 1);
                    float2 f = *(const float2*)&freqs[(size_t)s * 64 + (d & 63)];
                    uint32_t hi, lo;
                    pack_hilo(v0 * f.x * QSCALE, v1 * f.y * QSCALE, hi, lo);
                    const size_t idx = (((size_t)b * NHEADS + h) * SEQ + s) * 64 + (d >> 1);
                    Qh[idx] = hi; Ql[idx] = lo;
                }
            }
        }
    }
}

// ---------------------------------------------------------------------------
// Tensor-core flash attention (causal), bf16 hi/lo 3-pass.
// CTA: 128 q-rows x one (b,h). 8 warps x 16 rows. KV blocks of 64,
// 3-region rotation (Q region recycled as 3rd stage). bx reversed for balance.
// ---------------------------------------------------------------------------
#define ATT_SMEM (3 * 65536)

__global__ __launch_bounds__(256, 1) void attn_tc(
    const uint32_t* __restrict__ Qhi, const uint32_t* __restrict__ Qlo,
    const uint32_t* __restrict__ Khi, const uint32_t* __restrict__ Klo,
    const uint32_t* __restrict__ Vhi, const uint32_t* __restrict__ Vlo,
    uint32_t* __restrict__ Ohi, uint32_t* __restrict__ Olo)
{
    extern __shared__ char sm[];
    const uint32_t smb = smem_to_u32(sm);
    const int tid = threadIdx.x;
    const int w = tid >> 5;
    const int lane = tid & 31;
    const int bx = gridDim.x - 1 - blockIdx.x;   // big tiles first
    const int by = blockIdx.y;
    const int b = by >> 5, h = by & 31, g = h >> 2;
    const int q0 = bx * 128;
    const int nb = 2 * bx + 2;

    // --- Q load into region 0 ---
    const size_t qbase = (((size_t)b * NHEADS + h) * SEQ + q0) * 64;
#pragma unroll
    for (int t = tid; t < 4096; t += 256) {
        const int plane = t >> 11;
        const int i = t & 2047;
        const int row = i >> 4, ck = i & 15;
        const uint32_t dst = smb + plane * 32768u + SWZ256(row * 256 + ck * 16);
        cp16(dst, (plane ? Qlo : Qhi) + qbase + (size_t)row * 64 + ck * 4);
    }
    CP_COMMIT;

    const size_t kvbase = ((size_t)b * NKVH + g) * KVLEN * 64;
    auto load_kv = [&](int jb, int region) {
        const uint32_t sb = smb + (uint32_t)region * 65536u;
        const int kv0 = jb * 64;
#pragma unroll
        for (int t = tid; t < 4096; t += 256) {
            const int plane = t >> 10;                 // Khi Klo Vhi Vlo
            const int i = t & 1023;
            const int row = i >> 4, ck = i & 15;
            const uint32_t dst = sb + plane * 16384u + SWZ256(row * 256 + ck * 16);
            const uint32_t* base = (plane < 2) ? (plane & 1 ? Klo : Khi)
                                               : (plane & 1 ? Vlo : Vhi);
            cp16(dst, base + kvbase + (size_t)(kv0 + row) * 64 + ck * 4);
        }
    };

    load_kv(0, 1); CP_COMMIT;
    load_kv(1, 2); CP_COMMIT;
    CP_WAIT(2);                 // Q done
    __syncthreads();

    // --- preload Q fragments from region 0 (then region 0 becomes a stage) ---
    const int wi = lane & 7, qq = lane >> 3;
    const int arow = w * 16 + wi + ((qq & 1) ? 8 : 0);
    const int akoff = (qq & 2) ? 16 : 0;
    uint32_t qh[8][4], ql[8][4];
#pragma unroll
    for (int ks = 0; ks < 8; ks++) {
        const uint32_t off = SWZ256(arow * 256 + ks * 32 + akoff);
        ldsm_x4(qh[ks][0], qh[ks][1], qh[ks][2], qh[ks][3], smb + off);
        ldsm_x4(ql[ks][0], ql[ks][1], ql[ks][2], ql[ks][3], smb + 32768u + off);
    }

    float oacc[16][4];
#pragma unroll
    for (int i = 0; i < 16; i++)
#pragma unroll
        for (int v = 0; v < 4; v++) oacc[i][v] = 0.0f;
    float mprev0 = -INFINITY, mprev1 = -INFINITY;
    float lsum0 = 0.0f, lsum1 = 0.0f;

    const int rl = lane >> 2, cl2 = (lane & 3) * 2;
    const int row0g = q0 + w * 16 + rl;
    const int row1g = row0g + 8;
    const int brow = wi + ((qq & 2) ? 8 : 0);
    const int bkoff = (qq & 1) ? 16 : 0;
    const int vkr = (lane & 7) + ((lane & 8) ? 8 : 0);
    const int vnoff = (lane & 16) ? 16 : 0;

    for (int jb = 0; jb < nb; ++jb) {
        if (jb < nb - 1) CP_WAIT(1); else CP_WAIT(0);
        __syncthreads();
        if (jb + 2 < nb) { load_kv(jb + 2, jb % 3); CP_COMMIT; }
        const uint32_t sb = smb + (uint32_t)((jb + 1) % 3) * 65536u;

        // --- S = Q @ K^T (3-pass) ---
        float sacc[8][4];
#pragma unroll
        for (int i = 0; i < 8; i++)
#pragma unroll
            for (int v = 0; v < 4; v++) sacc[i][v] = 0.0f;
#pragma unroll
        for (int ks = 0; ks < 8; ks++) {
#pragma unroll
            for (int nt2 = 0; nt2 < 4; nt2++) {
                const uint32_t off = SWZ256((nt2 * 16 + brow) * 256 + ks * 32 + bkoff);
                uint32_t bh[4], bl[4];
                ldsm_x4(bh[0], bh[1], bh[2], bh[3], sb + off);
                ldsm_x4(bl[0], bl[1], bl[2], bl[3], sb + 16384u + off);
                mma_bf16(sacc[nt2 * 2],     qh[ks], bh[0], bh[1]);
                mma_bf16(sacc[nt2 * 2 + 1], qh[ks], bh[2], bh[3]);
                mma_bf16(sacc[nt2 * 2],     qh[ks], bl[0], bl[1]);
                mma_bf16(sacc[nt2 * 2 + 1], qh[ks], bl[2], bl[3]);
                mma_bf16(sacc[nt2 * 2],     ql[ks], bh[0], bh[1]);
                mma_bf16(sacc[nt2 * 2 + 1], ql[ks], bh[2], bh[3]);
            }
        }

        // --- causal mask ---
        if (jb >= 2 * bx) {
            const int kv0 = jb * 64;
#pragma unroll
            for (int nt = 0; nt < 8; nt++) {
                const int c0 = kv0 + nt * 8 + cl2;
                const int c1 = c0 + 1;
                if (c0 > row0g) sacc[nt][0] = -1e30f;
                if (c1 > row0g) sacc[nt][1] = -1e30f;
                if (c0 > row1g) sacc[nt][2] = -1e30f;
                if (c1 > row1g) sacc[nt][3] = -1e30f;
            }
        }

        // --- online softmax ---
        float mx0 = -1e30f, mx1 = -1e30f;
#pragma unroll
        for (int nt = 0; nt < 8; nt++) {
            mx0 = fmaxf(mx0, fmaxf(sacc[nt][0], sacc[nt][1]));
            mx1 = fmaxf(mx1, fmaxf(sacc[nt][2], sacc[nt][3]));
        }
        mx0 = fmaxf(mx0, __shfl_xor_sync(0xffffffffu, mx0, 1));
        mx0 = fmaxf(mx0, __shfl_xor_sync(0xffffffffu, mx0, 2));
        mx1 = fmaxf(mx1, __shfl_xor_sync(0xffffffffu, mx1, 1));
        mx1 = fmaxf(mx1, __shfl_xor_sync(0xffffffffu, mx1, 2));
        const float mnew0 = fmaxf(mprev0, mx0);
        const float mnew1 = fmaxf(mprev1, mx1);
        const float alpha0 = __expf(mprev0 - mnew0);
        const float alpha1 = __expf(mprev1 - mnew1);
        float rs0 = 0.0f, rs1 = 0.0f;
#pragma unroll
        for (int nt = 0; nt < 8; nt++) {
            sacc[nt][0] = __expf(sacc[nt][0] - mnew0);
            sacc[nt][1] = __expf(sacc[nt][1] - mnew0);
            sacc[nt][2] = __expf(sacc[nt][2] - mnew1);
            sacc[nt][3] = __expf(sacc[nt][3] - mnew1);
            rs0 += sacc[nt][0] + sacc[nt][1];
            rs1 += sacc[nt][2] + sacc[nt][3];
        }
        rs0 += __shfl_xor_sync(0xffffffffu, rs0, 1);
        rs0 += __shfl_xor_sync(0xffffffffu, rs0, 2);
        rs1 += __shfl_xor_sync(0xffffffffu, rs1, 1);
        rs1 += __shfl_xor_sync(0xffffffffu, rs1, 2);
        lsum0 = lsum0 * alpha0 + rs0;
        lsum1 = lsum1 * alpha1 + rs1;
#pragma unroll
        for (int nt = 0; nt < 16; nt++) {
            oacc[nt][0] *= alpha0; oacc[nt][1] *= alpha0;
            oacc[nt][2] *= alpha1; oacc[nt][3] *= alpha1;
        }
        mprev0 = mnew0; mprev1 = mnew1;

        // --- O += P @ V (3-pass) ---
#pragma unroll
        for (int jp = 0; jp < 4; jp++) {
            uint32_t pah[4], pal[4];
            pack_hilo(sacc[2 * jp][0],     sacc[2 * jp][1],     pah[0], pal[0]);
            pack_hilo(sacc[2 * jp][2],     sacc[2 * jp][3],     pah[1], pal[1]);
            pack_hilo(sacc[2 * jp + 1][0], sacc[2 * jp + 1][1], pah[2], pal[2]);
            pack_hilo(sacc[2 * jp + 1][2], sacc[2 * jp + 1][3], pah[3], pal[3]);
#pragma unroll
            for (int nt2 = 0; nt2 < 8; nt2++) {
                const uint32_t off = SWZ256((jp * 16 + vkr) * 256 + nt2 * 32 + vnoff);
                uint32_t vh[4], vl[4];
                ldsm_x4_t(vh[0], vh[1], vh[2], vh[3], sb + 32768u + off);
                ldsm_x4_t(vl[0], vl[1], vl[2], vl[3], sb + 49152u + off);
                mma_bf16(oacc[nt2 * 2],     pah, vh[0], vh[1]);
                mma_bf16(oacc[nt2 * 2 + 1], pah, vh[2], vh[3]);
                mma_bf16(oacc[nt2 * 2],     pal, vh[0], vh[1]);
                mma_bf16(oacc[nt2 * 2 + 1], pal, vh[2], vh[3]);
                mma_bf16(oacc[nt2 * 2],     pah, vl[0], vl[1]);
                mma_bf16(oacc[nt2 * 2 + 1], pah, vl[2], vl[3]);
            }
        }
    }

    // --- epilogue ---
    const float inv0 = 1.0f / lsum0;
    const float inv1 = 1.0f / lsum1;
    const size_t r0 = ((size_t)b * SEQ + row0g) * 2048 + h * 64;
    const size_t r1 = ((size_t)b * SEQ + row1g) * 2048 + h * 64;
#pragma unroll
    for (int nt = 0; nt < 16; nt++) {
        const int d2 = (nt * 8 + cl2) >> 1;
        uint32_t hi0, lo0, hi1, lo1;
        pack_hilo(oacc[nt][0] * inv0, oacc[nt][1] * inv0, hi0, lo0);
        pack_hilo(oacc[nt][2] * inv1, oacc[nt][3] * inv1, hi1, lo1);
        Ohi[r0 + d2] = hi0; Olo[r0 + d2] = lo0;
        Ohi[r1 + d2] = hi1; Olo[r1 + d2] = lo1;
    }
}

// ---------------------------------------------------------------------------
extern "C" void kernel_launch(void* const* d_in, const int* in_sizes, int n_in,
                              void* d_out, int out_size)
{
    (void)in_sizes; (void)n_in; (void)out_size;
    const float* x     = (const float*)d_in[0];
    const float* freqs = (const float*)d_in[1];
    const float* wq    = (const float*)d_in[3];
    const float* wo    = (const float*)d_in[6];
    const float* ck    = (const float*)d_in[7];
    const float* cv    = (const float*)d_in[8];
    float* out = (float*)d_out;

    void *xhi, *xlo, *wqhi, *wqlo, *wohi, *wolo, *qhi, *qlo, *ahi, *alo;
    void *khi, *klo, *vhi, *vlo;
    cudaGetSymbolAddress(&xhi, g_xhi);   cudaGetSymbolAddress(&xlo, g_xlo);
    cudaGetSymbolAddress(&wqhi, g_wqhi); cudaGetSymbolAddress(&wqlo, g_wqlo);
    cudaGetSymbolAddress(&wohi, g_wohi); cudaGetSymbolAddress(&wolo, g_wolo);
    cudaGetSymbolAddress(&qhi, g_qhi);   cudaGetSymbolAddress(&qlo, g_qlo);
    cudaGetSymbolAddress(&ahi, g_ahi);   cudaGetSymbolAddress(&alo, g_alo);
    cudaGetSymbolAddress(&khi, g_khi);   cudaGetSymbolAddress(&klo, g_klo);
    cudaGetSymbolAddress(&vhi, g_vhi);   cudaGetSymbolAddress(&vlo, g_vlo);

    cudaFuncSetAttribute(gemm_bf16<0>, cudaFuncAttributeMaxDynamicSharedMemorySize, GEMM_SMEM);
    cudaFuncSetAttribute(gemm_bf16<1>, cudaFuncAttributeMaxDynamicSharedMemorySize, GEMM_SMEM);
    cudaFuncSetAttribute(attn_tc, cudaFuncAttributeMaxDynamicSharedMemorySize, ATT_SMEM);

    dim3 blk(256);
    conv3<<<dim3(2048, 3), blk>>>(
        (const float4*)x, (const float4*)wq, (const float4*)wo,
        (uint2*)xhi, (uint2*)xlo, (uint2*)wqhi, (uint2*)wqlo,
        (uint2*)wohi, (uint2*)wolo);
    conv_kv4<<<dim3(1024, 2), blk>>>(
        (const float4*)ck, (const float4*)cv,
        (uint2*)khi, (uint2*)klo, (uint2*)vhi, (uint2*)vlo);

    gemm_bf16<1><<<dim3(16, 32), blk, GEMM_SMEM>>>(
        (const uint32_t*)xhi, (const uint32_t*)xlo,
        (const uint32_t*)wqhi, (const uint32_t*)wqlo,
        nullptr, freqs, (uint32_t*)qhi, (uint32_t*)qlo);

    attn_tc<<<dim3(16, 64), blk, ATT_SMEM>>>(
        (const uint32_t*)qhi, (const uint32_t*)qlo,
        (const uint32_t*)khi, (const uint32_t*)klo,
        (const uint32_t*)vhi, (const uint32_t*)vlo,
        (uint32_t*)ahi, (uint32_t*)alo);

    gemm_bf16<0><<<dim3(16, 32), blk, GEMM_SMEM>>>(
        (const uint32_t*)ahi, (const uint32_t*)alo,
        (const uint32_t*)wohi, (const uint32_t*)wolo,
        out, nullptr, nullptr, nullptr);
}

// round 8
// speedup vs baseline: 1.0680x; 1.0680x over previous
#include <cuda_runtime.h>
#include <cuda_bf16.h>
#include <math.h>
#include <stdint.h>

#define BATCH 2
#define SEQ   2048
#define DMODEL 4096
#define NHEADS 32
#define NKVH  8
#define HEADD 128
#define KVLEN 2048

// QSCALE * log2(e): softmax done in base-2
#define QSC2 (0.08838834764831845f * 1.4426950408889634f)

// ---------------------------------------------------------------------------
// Global scratch: bf16 hi/lo planes stored as packed bf16x2 (uint32).
// ---------------------------------------------------------------------------
#define PLANE_U32 (8388608)
__device__ uint32_t g_xhi[PLANE_U32],  g_xlo[PLANE_U32];   // x rows (b*s, k)
__device__ uint32_t g_wqhi[PLANE_U32], g_wqlo[PLANE_U32];  // wq (n, k)
__device__ uint32_t g_wohi[PLANE_U32], g_wolo[PLANE_U32];  // wo (n, k)
__device__ uint32_t g_qhi[PLANE_U32],  g_qlo[PLANE_U32];   // q (b,h,s,d)
__device__ uint32_t g_ahi[PLANE_U32],  g_alo[PLANE_U32];   // attn out (b*s, h*d)
#define KV_U32 (2097152)
__device__ uint32_t g_khi[KV_U32], g_klo[KV_U32];          // (b,g,s,d)
__device__ uint32_t g_vhi[KV_U32], g_vlo[KV_U32];

// ---------------------------------------------------------------------------
__device__ __forceinline__ uint32_t smem_to_u32(const void* p) {
    uint32_t a;
    asm("{ .reg .u64 t; cvta.to.shared.u64 t, %1; cvt.u32.u64 %0, t; }" : "=r"(a) : "l"(p));
    return a;
}
#define SWZ64(off)  ((uint32_t)(off) ^ ((((uint32_t)(off)) >> 3) & 0x30u))
#define SWZ256(off) ((uint32_t)(off) ^ ((((uint32_t)(off)) >> 4) & 0x70u))

__device__ __forceinline__ void cp16(uint32_t dst, const void* src) {
    asm volatile("cp.async.cg.shared.global [%0], [%1], 16;" :: "r"(dst), "l"(src));
}
#define CP_COMMIT asm volatile("cp.async.commit_group;" ::: "memory")
#define CP_WAIT(n) asm volatile("cp.async.wait_group %0;" :: "n"(n) : "memory")

__device__ __forceinline__ void ldsm_x4(uint32_t& r0, uint32_t& r1, uint32_t& r2, uint32_t& r3,
                                        uint32_t addr) {
    asm volatile("ldmatrix.sync.aligned.m8n8.x4.shared.b16 {%0,%1,%2,%3}, [%4];"
                 : "=r"(r0), "=r"(r1), "=r"(r2), "=r"(r3) : "r"(addr));
}
__device__ __forceinline__ void ldsm_x4_t(uint32_t& r0, uint32_t& r1, uint32_t& r2, uint32_t& r3,
                                          uint32_t addr) {
    asm volatile("ldmatrix.sync.aligned.m8n8.x4.trans.shared.b16 {%0,%1,%2,%3}, [%4];"
                 : "=r"(r0), "=r"(r1), "=r"(r2), "=r"(r3) : "r"(addr));
}
__device__ __forceinline__ void mma_bf16(float* d, const uint32_t* a, uint32_t b0, uint32_t b1) {
    asm volatile(
        "mma.sync.aligned.m16n8k16.row.col.f32.bf16.bf16.f32 "
        "{%0,%1,%2,%3}, {%4,%5,%6,%7}, {%8,%9}, {%0,%1,%2,%3};"
        : "+f"(d[0]), "+f"(d[1]), "+f"(d[2]), "+f"(d[3])
        : "r"(a[0]), "r"(a[1]), "r"(a[2]), "r"(a[3]), "r"(b0), "r"(b1));
}
__device__ __forceinline__ void pack_hilo(float a, float b, uint32_t& hi, uint32_t& lo) {
    uint32_t h;
    asm("cvt.rn.bf16x2.f32 %0, %1, %2;" : "=r"(h) : "f"(b), "f"(a));
    float fa = __uint_as_float(h << 16);
    float fb = __uint_as_float(h & 0xffff0000u);
    float ra = a - fa;
    float rb = b - fb;
    uint32_t l;
    asm("cvt.rn.bf16x2.f32 %0, %1, %2;" : "=r"(l) : "f"(rb), "f"(ra));
    hi = h; lo = l;
}

// ---------------------------------------------------------------------------
// Fused conversion kernels (float4-wide)
// ---------------------------------------------------------------------------
__global__ void conv3(const float4* __restrict__ s0, const float4* __restrict__ s1,
                      const float4* __restrict__ s2,
                      uint2* h0, uint2* l0, uint2* h1, uint2* l1, uint2* h2, uint2* l2)
{
    const float4* src = (blockIdx.y == 0) ? s0 : (blockIdx.y == 1) ? s1 : s2;
    uint2* hi = (blockIdx.y == 0) ? h0 : (blockIdx.y == 1) ? h1 : h2;
    uint2* lo = (blockIdx.y == 0) ? l0 : (blockIdx.y == 1) ? l1 : l2;
    const int n4 = PLANE_U32 / 2;
    for (int i = blockIdx.x * blockDim.x + threadIdx.x; i < n4;
         i += gridDim.x * blockDim.x) {
        float4 v = src[i];
        uint32_t ha, la, hb, lb;
        pack_hilo(v.x, v.y, ha, la);
        pack_hilo(v.z, v.w, hb, lb);
        hi[i] = make_uint2(ha, hb);
        lo[i] = make_uint2(la, lb);
    }
}

// cache (b,s,g,d) fp32 -> planes (b,g,s,d)
__global__ void conv_kv4(const float4* __restrict__ ksrc, const float4* __restrict__ vsrc,
                         uint2* kh, uint2* kl, uint2* vh, uint2* vl)
{
    const float4* src = blockIdx.y ? vsrc : ksrc;
    uint2* hi = blockIdx.y ? vh : kh;
    uint2* lo = blockIdx.y ? vl : kl;
    const int n4 = KV_U32 / 2;
    for (int p = blockIdx.x * blockDim.x + threadIdx.x; p < n4;
         p += gridDim.x * blockDim.x) {
        const int d4 = p & 31;
        const int s = (p >> 5) & 2047;
        const int g = (p >> 16) & 7;
        const int b = p >> 19;
        float4 v = src[(((size_t)b * SEQ + s) * NKVH + g) * 32 + d4];
        uint32_t ha, la, hb, lb;
        pack_hilo(v.x, v.y, ha, la);
        pack_hilo(v.z, v.w, hb, lb);
        hi[p] = make_uint2(ha, hb);
        lo[p] = make_uint2(la, lb);
    }
}

// ---------------------------------------------------------------------------
// Pipelined bf16-split GEMM: C[M,N] = A[M,K] @ B[N,K]^T  (4096^3)
// 3 passes. CTA 128x128, 8 warps (32x64 each), K-chunk 32,
// 3-stage cp.async (32KB stages, SW64), 2 CTAs/SM.
// Stage layout: Ahi[8K] Alo[8K] Bhi[8K] Blo[8K].
// EPI=0: fp32 store.  EPI=1: Q-proj (freqs * QSC2 -> bf16 hi/lo Qh/Ql).
// ---------------------------------------------------------------------------
#define GEMM_SMEM (3 * 32768)

template <int EPI>
__global__ __launch_bounds__(256, 2) void gemm_bf16(
    const uint32_t* __restrict__ Ahi, const uint32_t* __restrict__ Alo,
    const uint32_t* __restrict__ Bhi, const uint32_t* __restrict__ Blo,
    float* __restrict__ C, const float* __restrict__ freqs,
    uint32_t* __restrict__ Qh, uint32_t* __restrict__ Ql)
{
    extern __shared__ char sm[];
    const uint32_t smb = smem_to_u32(sm);
    const int tid = threadIdx.x;
    const int wid = tid >> 5;
    const int lane = tid & 31;
    const int wn = wid & 1;          // n half (64)
    const int wm = wid >> 1;         // m quarter (32)
    const int m0 = blockIdx.y * 128;
    const int n0 = blockIdx.x * 128;

    float acc[2][8][4];
#pragma unroll
    for (int i = 0; i < 2; i++)
#pragma unroll
        for (int j = 0; j < 8; j++)
#pragma unroll
            for (int v = 0; v < 4; v++) acc[i][j][v] = 0.0f;

    auto load_stage = [&](int ch, int st) {
        const uint32_t sbase = smb + (uint32_t)st * 32768u;
        const int kc2 = ch * 16;
#pragma unroll
        for (int t = tid; t < 2048; t += 256) {
            const int plane = t >> 9;            // Ahi Alo Bhi Blo
            const int i = t & 511;
            const int row = i >> 2, ck = i & 3;
            const uint32_t dst = sbase + plane * 8192u + SWZ64(row * 64 + ck * 16);
            const uint32_t* bp = (plane == 0) ? Ahi : (plane == 1) ? Alo
                                : (plane == 2) ? Bhi : Blo;
            const int r0 = (plane < 2) ? m0 : n0;
            cp16(dst, bp + (size_t)(r0 + row) * 2048 + kc2 + ck * 4);
        }
    };

    const int q = lane >> 3;
    const int wi = lane & 7;
    const int arow_base = wm * 32 + wi + ((q & 1) ? 8 : 0);
    const int akb_off = (q & 2) ? 16 : 0;
    const int brow_base = wn * 64 + wi + ((q & 2) ? 8 : 0);
    const int bkb_off = (q & 1) ? 16 : 0;

    load_stage(0, 0); CP_COMMIT;
    load_stage(1, 1); CP_COMMIT;

    for (int ch = 0; ch < 128; ++ch) {
        if (ch < 127) CP_WAIT(1); else CP_WAIT(0);
        __syncthreads();
        if (ch + 2 < 128) { load_stage(ch + 2, (ch + 2) % 3); CP_COMMIT; }

        const uint32_t sbase = smb + (uint32_t)(ch % 3) * 32768u;
        const uint32_t pAhi = sbase,           pAlo = sbase + 8192u;
        const uint32_t pBhi = sbase + 16384u,  pBlo = sbase + 24576u;

#pragma unroll
        for (int ks = 0; ks < 2; ++ks) {
            const int kb0 = ks * 32;
            uint32_t ah[2][4], al[2][4];
#pragma unroll
            for (int mt = 0; mt < 2; ++mt) {
                const int r = arow_base + mt * 16;
                const uint32_t off = SWZ64(r * 64 + kb0 + akb_off);
                ldsm_x4(ah[mt][0], ah[mt][1], ah[mt][2], ah[mt][3], pAhi + off);
                ldsm_x4(al[mt][0], al[mt][1], al[mt][2], al[mt][3], pAlo + off);
            }
#pragma unroll
            for (int np = 0; np < 4; ++np) {
                const int rn = brow_base + np * 16;
                const uint32_t offb = SWZ64(rn * 64 + kb0 + bkb_off);
                uint32_t bh[4], bl[4];
                ldsm_x4(bh[0], bh[1], bh[2], bh[3], pBhi + offb);
                ldsm_x4(bl[0], bl[1], bl[2], bl[3], pBlo + offb);
#pragma unroll
                for (int mt = 0; mt < 2; ++mt) {
                    mma_bf16(acc[mt][np * 2],     ah[mt], bh[0], bh[1]);
                    mma_bf16(acc[mt][np * 2 + 1], ah[mt], bh[2], bh[3]);
                    mma_bf16(acc[mt][np * 2],     ah[mt], bl[0], bl[1]);
                    mma_bf16(acc[mt][np * 2 + 1], ah[mt], bl[2], bl[3]);
                    mma_bf16(acc[mt][np * 2],     al[mt], bh[0], bh[1]);
                    mma_bf16(acc[mt][np * 2 + 1], al[mt], bh[2], bh[3]);
                }
            }
        }
    }

    // epilogue from registers
    const int rl = lane >> 2;
    const int cl = (lane & 3) * 2;
#pragma unroll
    for (int mt = 0; mt < 2; ++mt) {
#pragma unroll
        for (int nn = 0; nn < 8; ++nn) {
            const int r = m0 + wm * 32 + mt * 16 + rl;
            const int c = n0 + wn * 64 + nn * 8 + cl;
#pragma unroll
            for (int half = 0; half < 2; ++half) {
                const int rr = r + half * 8;
                const float v0 = acc[mt][nn][half * 2];
                const float v1 = acc[mt][nn][half * 2 + 1];
                if (EPI == 0) {
                    *(float2*)&C[(size_t)rr * DMODEL + c] = make_float2(v0, v1);
                } else {
                    const int b = rr >> 11;
                    const int s = rr & (SEQ - 1);
                    const int h = c >> 7;
                    const int d = c & (HEADD - 1);
                    float2 f = *(const float2*)&freqs[(size_t)s * 64 + (d & 63)];
                    uint32_t hi, lo;
                    pack_hilo(v0 * f.x * QSC2, v1 * f.y * QSC2, hi, lo);
                    const size_t idx = (((size_t)b * NHEADS + h) * SEQ + s) * 64 + (d >> 1);
                    Qh[idx] = hi; Ql[idx] = lo;
                }
            }
        }
    }
}

// ---------------------------------------------------------------------------
// Tensor-core flash attention (causal), bf16 hi/lo 3-pass, base-2 softmax.
// CTA: 128 q-rows x one (b,h). 8 warps x 16 rows. KV blocks of 64,
// 3-region rotation (Q region recycled as 3rd stage). bx reversed for balance.
// ---------------------------------------------------------------------------
#define ATT_SMEM (3 * 65536)

__global__ __launch_bounds__(256, 1) void attn_tc(
    const uint32_t* __restrict__ Qhi, const uint32_t* __restrict__ Qlo,
    const uint32_t* __restrict__ Khi, const uint32_t* __restrict__ Klo,
    const uint32_t* __restrict__ Vhi, const uint32_t* __restrict__ Vlo,
    uint32_t* __restrict__ Ohi, uint32_t* __restrict__ Olo)
{
    extern __shared__ char sm[];
    const uint32_t smb = smem_to_u32(sm);
    const int tid = threadIdx.x;
    const int w = tid >> 5;
    const int lane = tid & 31;
    const int bx = gridDim.x - 1 - blockIdx.x;   // big tiles first
    const int by = blockIdx.y;
    const int b = by >> 5, h = by & 31, g = h >> 2;
    const int q0 = bx * 128;
    const int nb = 2 * bx + 2;

    // --- Q load into region 0 ---
    const size_t qbase = (((size_t)b * NHEADS + h) * SEQ + q0) * 64;
#pragma unroll
    for (int t = tid; t < 4096; t += 256) {
        const int plane = t >> 11;
        const int i = t & 2047;
        const int row = i >> 4, ck = i & 15;
        const uint32_t dst = smb + plane * 32768u + SWZ256(row * 256 + ck * 16);
        cp16(dst, (plane ? Qlo : Qhi) + qbase + (size_t)row * 64 + ck * 4);
    }
    CP_COMMIT;

    const size_t kvbase = ((size_t)b * NKVH + g) * KVLEN * 64;
    auto load_kv = [&](int jb, int region) {
        const uint32_t sb = smb + (uint32_t)region * 65536u;
        const int kv0 = jb * 64;
#pragma unroll
        for (int t = tid; t < 4096; t += 256) {
            const int plane = t >> 10;                 // Khi Klo Vhi Vlo
            const int i = t & 1023;
            const int row = i >> 4, ck = i & 15;
            const uint32_t dst = sb + plane * 16384u + SWZ256(row * 256 + ck * 16);
            const uint32_t* base = (plane < 2) ? (plane & 1 ? Klo : Khi)
                                               : (plane & 1 ? Vlo : Vhi);
            cp16(dst, base + kvbase + (size_t)(kv0 + row) * 64 + ck * 4);
        }
    };

    load_kv(0, 1); CP_COMMIT;
    load_kv(1, 2); CP_COMMIT;
    CP_WAIT(2);                 // Q done
    __syncthreads();

    // --- preload Q fragments from region 0 (then region 0 becomes a stage) ---
    const int wi = lane & 7, qq = lane >> 3;
    const int arow = w * 16 + wi + ((qq & 1) ? 8 : 0);
    const int akoff = (qq & 2) ? 16 : 0;
    uint32_t qh[8][4], ql[8][4];
#pragma unroll
    for (int ks = 0; ks < 8; ks++) {
        const uint32_t off = SWZ256(arow * 256 + ks * 32 + akoff);
        ldsm_x4(qh[ks][0], qh[ks][1], qh[ks][2], qh[ks][3], smb + off);
        ldsm_x4(ql[ks][0], ql[ks][1], ql[ks][2], ql[ks][3], smb + 32768u + off);
    }

    float oacc[16][4];
#pragma unroll
    for (int i = 0; i < 16; i++)
#pragma unroll
        for (int v = 0; v < 4; v++) oacc[i][v] = 0.0f;
    float mprev0 = -INFINITY, mprev1 = -INFINITY;
    float lsum0 = 0.0f, lsum1 = 0.0f;

    const int rl = lane >> 2, cl2 = (lane & 3) * 2;
    const int row0g = q0 + w * 16 + rl;
    const int row1g = row0g + 8;
    const int brow = wi + ((qq & 2) ? 8 : 0);
    const int bkoff = (qq & 1) ? 16 : 0;
    const int vkr = (lane & 7) + ((lane & 8) ? 8 : 0);
    const int vnoff = (lane & 16) ? 16 : 0;

    for (int jb = 0; jb < nb; ++jb) {
        if (jb < nb - 1) CP_WAIT(1); else CP_WAIT(0);
        __syncthreads();
        if (jb + 2 < nb) { load_kv(jb + 2, jb % 3); CP_COMMIT; }
        const uint32_t sb = smb + (uint32_t)((jb + 1) % 3) * 65536u;

        // --- S = Q @ K^T (3-pass), scores already in log2 domain ---
        float sacc[8][4];
#pragma unroll
        for (int i = 0; i < 8; i++)
#pragma unroll
            for (int v = 0; v < 4; v++) sacc[i][v] = 0.0f;
#pragma unroll
        for (int ks = 0; ks < 8; ks++) {
#pragma unroll
            for (int nt2 = 0; nt2 < 4; nt2++) {
                const uint32_t off = SWZ256((nt2 * 16 + brow) * 256 + ks * 32 + bkoff);
                uint32_t bh[4], bl[4];
                ldsm_x4(bh[0], bh[1], bh[2], bh[3], sb + off);
                ldsm_x4(bl[0], bl[1], bl[2], bl[3], sb + 16384u + off);
                mma_bf16(sacc[nt2 * 2],     qh[ks], bh[0], bh[1]);
                mma_bf16(sacc[nt2 * 2 + 1], qh[ks], bh[2], bh[3]);
                mma_bf16(sacc[nt2 * 2],     qh[ks], bl[0], bl[1]);
                mma_bf16(sacc[nt2 * 2 + 1], qh[ks], bl[2], bl[3]);
                mma_bf16(sacc[nt2 * 2],     ql[ks], bh[0], bh[1]);
                mma_bf16(sacc[nt2 * 2 + 1], ql[ks], bh[2], bh[3]);
            }
        }

        // --- causal mask ---
        if (jb >= 2 * bx) {
            const int kv0 = jb * 64;
#pragma unroll
            for (int nt = 0; nt < 8; nt++) {
                const int c0 = kv0 + nt * 8 + cl2;
                const int c1 = c0 + 1;
                if (c0 > row0g) sacc[nt][0] = -1e30f;
                if (c1 > row0g) sacc[nt][1] = -1e30f;
                if (c0 > row1g) sacc[nt][2] = -1e30f;
                if (c1 > row1g) sacc[nt][3] = -1e30f;
            }
        }

        // --- online softmax (base 2) ---
        float mx0 = -1e30f, mx1 = -1e30f;
#pragma unroll
        for (int nt = 0; nt < 8; nt++) {
            mx0 = fmaxf(mx0, fmaxf(sacc[nt][0], sacc[nt][1]));
            mx1 = fmaxf(mx1, fmaxf(sacc[nt][2], sacc[nt][3]));
        }
        mx0 = fmaxf(mx0, __shfl_xor_sync(0xffffffffu, mx0, 1));
        mx0 = fmaxf(mx0, __shfl_xor_sync(0xffffffffu, mx0, 2));
        mx1 = fmaxf(mx1, __shfl_xor_sync(0xffffffffu, mx1, 1));
        mx1 = fmaxf(mx1, __shfl_xor_sync(0xffffffffu, mx1, 2));
        const float mnew0 = fmaxf(mprev0, mx0);
        const float mnew1 = fmaxf(mprev1, mx1);
        const float alpha0 = exp2f(mprev0 - mnew0);
        const float alpha1 = exp2f(mprev1 - mnew1);
        float rs0 = 0.0f, rs1 = 0.0f;
#pragma unroll
        for (int nt = 0; nt < 8; nt++) {
            sacc[nt][0] = exp2f(sacc[nt][0] - mnew0);
            sacc[nt][1] = exp2f(sacc[nt][1] - mnew0);
            sacc[nt][2] = exp2f(sacc[nt][2] - mnew1);
            sacc[nt][3] = exp2f(sacc[nt][3] - mnew1);
            rs0 += sacc[nt][0] + sacc[nt][1];
            rs1 += sacc[nt][2] + sacc[nt][3];
        }
        rs0 += __shfl_xor_sync(0xffffffffu, rs0, 1);
        rs0 += __shfl_xor_sync(0xffffffffu, rs0, 2);
        rs1 += __shfl_xor_sync(0xffffffffu, rs1, 1);
        rs1 += __shfl_xor_sync(0xffffffffu, rs1, 2);
        lsum0 = lsum0 * alpha0 + rs0;
        lsum1 = lsum1 * alpha1 + rs1;
#pragma unroll
        for (int nt = 0; nt < 16; nt++) {
            oacc[nt][0] *= alpha0; oacc[nt][1] *= alpha0;
            oacc[nt][2] *= alpha1; oacc[nt][3] *= alpha1;
        }
        mprev0 = mnew0; mprev1 = mnew1;

        // --- O += P @ V (3-pass) ---
#pragma unroll
        for (int jp = 0; jp < 4; jp++) {
            uint32_t pah[4], pal[4];
            pack_hilo(sacc[2 * jp][0],     sacc[2 * jp][1],     pah[0], pal[0]);
            pack_hilo(sacc[2 * jp][2],     sacc[2 * jp][3],     pah[1], pal[1]);
            pack_hilo(sacc[2 * jp + 1][0], sacc[2 * jp + 1][1], pah[2], pal[2]);
            pack_hilo(sacc[2 * jp + 1][2], sacc[2 * jp + 1][3], pah[3], pal[3]);
#pragma unroll
            for (int nt2 = 0; nt2 < 8; nt2++) {
                const uint32_t off = SWZ256((jp * 16 + vkr) * 256 + nt2 * 32 + vnoff);
                uint32_t vh[4], vl[4];
                ldsm_x4_t(vh[0], vh[1], vh[2], vh[3], sb + 32768u + off);
                ldsm_x4_t(vl[0], vl[1], vl[2], vl[3], sb + 49152u + off);
                mma_bf16(oacc[nt2 * 2],     pah, vh[0], vh[1]);
                mma_bf16(oacc[nt2 * 2 + 1], pah, vh[2], vh[3]);
                mma_bf16(oacc[nt2 * 2],     pal, vh[0], vh[1]);
                mma_bf16(oacc[nt2 * 2 + 1], pal, vh[2], vh[3]);
                mma_bf16(oacc[nt2 * 2],     pah, vl[0], vl[1]);
                mma_bf16(oacc[nt2 * 2 + 1], pah, vl[2], vl[3]);
            }
        }
    }

    // --- epilogue ---
    const float inv0 = 1.0f / lsum0;
    const float inv1 = 1.0f / lsum1;
    const size_t r0 = ((size_t)b * SEQ + row0g) * 2048 + h * 64;
    const size_t r1 = ((size_t)b * SEQ + row1g) * 2048 + h * 64;
#pragma unroll
    for (int nt = 0; nt < 16; nt++) {
        const int d2 = (nt * 8 + cl2) >> 1;
        uint32_t hi0, lo0, hi1, lo1;
        pack_hilo(oacc[nt][0] * inv0, oacc[nt][1] * inv0, hi0, lo0);
        pack_hilo(oacc[nt][2] * inv1, oacc[nt][3] * inv1, hi1, lo1);
        Ohi[r0 + d2] = hi0; Olo[r0 + d2] = lo0;
        Ohi[r1 + d2] = hi1; Olo[r1 + d2] = lo1;
    }
}

// ---------------------------------------------------------------------------
extern "C" void kernel_launch(void* const* d_in, const int* in_sizes, int n_in,
                              void* d_out, int out_size)
{
    (void)in_sizes; (void)n_in; (void)out_size;
    const float* x     = (const float*)d_in[0];
    const float* freqs = (const float*)d_in[1];
    const float* wq    = (const float*)d_in[3];
    const float* wo    = (const float*)d_in[6];
    const float* ck    = (const float*)d_in[7];
    const float* cv    = (const float*)d_in[8];
    float* out = (float*)d_out;

    void *xhi, *xlo, *wqhi, *wqlo, *wohi, *wolo, *qhi, *qlo, *ahi, *alo;
    void *khi, *klo, *vhi, *vlo;
    cudaGetSymbolAddress(&xhi, g_xhi);   cudaGetSymbolAddress(&xlo, g_xlo);
    cudaGetSymbolAddress(&wqhi, g_wqhi); cudaGetSymbolAddress(&wqlo, g_wqlo);
    cudaGetSymbolAddress(&wohi, g_wohi); cudaGetSymbolAddress(&wolo, g_wolo);
    cudaGetSymbolAddress(&qhi, g_qhi);   cudaGetSymbolAddress(&qlo, g_qlo);
    cudaGetSymbolAddress(&ahi, g_ahi);   cudaGetSymbolAddress(&alo, g_alo);
    cudaGetSymbolAddress(&khi, g_khi);   cudaGetSymbolAddress(&klo, g_klo);
    cudaGetSymbolAddress(&vhi, g_vhi);   cudaGetSymbolAddress(&vlo, g_vlo);

    cudaFuncSetAttribute(gemm_bf16<0>, cudaFuncAttributeMaxDynamicSharedMemorySize, GEMM_SMEM);
    cudaFuncSetAttribute(gemm_bf16<1>, cudaFuncAttributeMaxDynamicSharedMemorySize, GEMM_SMEM);
    cudaFuncSetAttribute(attn_tc, cudaFuncAttributeMaxDynamicSharedMemorySize, ATT_SMEM);

    dim3 blk(256);
    conv3<<<dim3(2048, 3), blk>>>(
        (const float4*)x, (const float4*)wq, (const float4*)wo,
        (uint2*)xhi, (uint2*)xlo, (uint2*)wqhi, (uint2*)wqlo,
        (uint2*)wohi, (uint2*)wolo);
    conv_kv4<<<dim3(1024, 2), blk>>>(
        (const float4*)ck, (const float4*)cv,
        (uint2*)khi, (uint2*)klo, (uint2*)vhi, (uint2*)vlo);

    gemm_bf16<1><<<dim3(32, 32), blk, GEMM_SMEM>>>(
        (const uint32_t*)xhi, (const uint32_t*)xlo,
        (const uint32_t*)wqhi, (const uint32_t*)wqlo,
        nullptr, freqs, (uint32_t*)qhi, (uint32_t*)qlo);

    attn_tc<<<dim3(16, 64), blk, ATT_SMEM>>>(
        (const uint32_t*)qhi, (const uint32_t*)qlo,
        (const uint32_t*)khi, (const uint32_t*)klo,
        (const uint32_t*)vhi, (const uint32_t*)vlo,
        (uint32_t*)ahi, (uint32_t*)alo);

    gemm_bf16<0><<<dim3(32, 32), blk, GEMM_SMEM>>>(
        (const uint32_t*)ahi, (const uint32_t*)alo,
        (const uint32_t*)wohi, (const uint32_t*)wolo,
        out, nullptr, nullptr, nullptr);
}

// round 9
// speedup vs baseline: 1.0997x; 1.0296x over previous
#include <cuda_runtime.h>
#include <cuda_bf16.h>
#include <math.h>
#include <stdint.h>

#define BATCH 2
#define SEQ   2048
#define DMODEL 4096
#define NHEADS 32
#define NKVH  8
#define HEADD 128
#define KVLEN 2048

// QSCALE * log2(e): softmax done in base-2
#define QSC2 (0.08838834764831845f * 1.4426950408889634f)

// ---------------------------------------------------------------------------
// Global scratch: bf16 hi/lo planes stored as packed bf16x2 (uint32).
// ---------------------------------------------------------------------------
#define PLANE_U32 (8388608)
__device__ uint32_t g_xhi[PLANE_U32],  g_xlo[PLANE_U32];   // x rows (b*s, k)
__device__ uint32_t g_wqhi[PLANE_U32], g_wqlo[PLANE_U32];  // wq (n, k)
__device__ uint32_t g_wohi[PLANE_U32], g_wolo[PLANE_U32];  // wo (n, k)
__device__ uint32_t g_qhi[PLANE_U32],  g_qlo[PLANE_U32];   // q (b,h,s,d)
__device__ uint32_t g_ahi[PLANE_U32],  g_alo[PLANE_U32];   // attn out (b*s, h*d)
#define KV_U32 (2097152)
__device__ uint32_t g_khi[KV_U32], g_klo[KV_U32];          // (b,g,s,d)
__device__ uint32_t g_vhi[KV_U32], g_vlo[KV_U32];

// ---------------------------------------------------------------------------
__device__ __forceinline__ uint32_t smem_to_u32(const void* p) {
    uint32_t a;
    asm("{ .reg .u64 t; cvta.to.shared.u64 t, %1; cvt.u32.u64 %0, t; }" : "=r"(a) : "l"(p));
    return a;
}
#define SWZ64(off)  ((uint32_t)(off) ^ ((((uint32_t)(off)) >> 3) & 0x30u))
#define SWZ256(off) ((uint32_t)(off) ^ ((((uint32_t)(off)) >> 4) & 0x70u))

__device__ __forceinline__ void cp16(uint32_t dst, const void* src) {
    asm volatile("cp.async.cg.shared.global [%0], [%1], 16;" :: "r"(dst), "l"(src));
}
#define CP_COMMIT asm volatile("cp.async.commit_group;" ::: "memory")
#define CP_WAIT(n) asm volatile("cp.async.wait_group %0;" :: "n"(n) : "memory")

__device__ __forceinline__ void ldsm_x4(uint32_t& r0, uint32_t& r1, uint32_t& r2, uint32_t& r3,
                                        uint32_t addr) {
    asm volatile("ldmatrix.sync.aligned.m8n8.x4.shared.b16 {%0,%1,%2,%3}, [%4];"
                 : "=r"(r0), "=r"(r1), "=r"(r2), "=r"(r3) : "r"(addr));
}
__device__ __forceinline__ void ldsm_x4_t(uint32_t& r0, uint32_t& r1, uint32_t& r2, uint32_t& r3,
                                          uint32_t addr) {
    asm volatile("ldmatrix.sync.aligned.m8n8.x4.trans.shared.b16 {%0,%1,%2,%3}, [%4];"
                 : "=r"(r0), "=r"(r1), "=r"(r2), "=r"(r3) : "r"(addr));
}
__device__ __forceinline__ void mma_bf16(float* d, const uint32_t* a, uint32_t b0, uint32_t b1) {
    asm volatile(
        "mma.sync.aligned.m16n8k16.row.col.f32.bf16.bf16.f32 "
        "{%0,%1,%2,%3}, {%4,%5,%6,%7}, {%8,%9}, {%0,%1,%2,%3};"
        : "+f"(d[0]), "+f"(d[1]), "+f"(d[2]), "+f"(d[3])
        : "r"(a[0]), "r"(a[1]), "r"(a[2]), "r"(a[3]), "r"(b0), "r"(b1));
}
__device__ __forceinline__ void pack_hilo(float a, float b, uint32_t& hi, uint32_t& lo) {
    uint32_t h;
    asm("cvt.rn.bf16x2.f32 %0, %1, %2;" : "=r"(h) : "f"(b), "f"(a));
    float fa = __uint_as_float(h << 16);
    float fb = __uint_as_float(h & 0xffff0000u);
    float ra = a - fa;
    float rb = b - fb;
    uint32_t l;
    asm("cvt.rn.bf16x2.f32 %0, %1, %2;" : "=r"(l) : "f"(rb), "f"(ra));
    hi = h; lo = l;
}

// ---------------------------------------------------------------------------
// Fused conversion kernels (float4-wide)
// ---------------------------------------------------------------------------
__global__ void conv3(const float4* __restrict__ s0, const float4* __restrict__ s1,
                      const float4* __restrict__ s2,
                      uint2* h0, uint2* l0, uint2* h1, uint2* l1, uint2* h2, uint2* l2)
{
    const float4* src = (blockIdx.y == 0) ? s0 : (blockIdx.y == 1) ? s1 : s2;
    uint2* hi = (blockIdx.y == 0) ? h0 : (blockIdx.y == 1) ? h1 : h2;
    uint2* lo = (blockIdx.y == 0) ? l0 : (blockIdx.y == 1) ? l1 : l2;
    const int n4 = PLANE_U32 / 2;
    for (int i = blockIdx.x * blockDim.x + threadIdx.x; i < n4;
         i += gridDim.x * blockDim.x) {
        float4 v = src[i];
        uint32_t ha, la, hb, lb;
        pack_hilo(v.x, v.y, ha, la);
        pack_hilo(v.z, v.w, hb, lb);
        hi[i] = make_uint2(ha, hb);
        lo[i] = make_uint2(la, lb);
    }
}

// cache (b,s,g,d) fp32 -> planes (b,g,s,d)
__global__ void conv_kv4(const float4* __restrict__ ksrc, const float4* __restrict__ vsrc,
                         uint2* kh, uint2* kl, uint2* vh, uint2* vl)
{
    const float4* src = blockIdx.y ? vsrc : ksrc;
    uint2* hi = blockIdx.y ? vh : kh;
    uint2* lo = blockIdx.y ? vl : kl;
    const int n4 = KV_U32 / 2;
    for (int p = blockIdx.x * blockDim.x + threadIdx.x; p < n4;
         p += gridDim.x * blockDim.x) {
        const int d4 = p & 31;
        const int s = (p >> 5) & 2047;
        const int g = (p >> 16) & 7;
        const int b = p >> 19;
        float4 v = src[(((size_t)b * SEQ + s) * NKVH + g) * 32 + d4];
        uint32_t ha, la, hb, lb;
        pack_hilo(v.x, v.y, ha, la);
        pack_hilo(v.z, v.w, hb, lb);
        hi[p] = make_uint2(ha, hb);
        lo[p] = make_uint2(la, lb);
    }
}

// ---------------------------------------------------------------------------
// Pipelined bf16-split GEMM: C[M,N] = A[M,K] @ B[N,K]^T  (4096^3)
// 3 passes. CTA 128x128, 8 warps (32x64 each), K-chunk 32,
// 3-stage cp.async (32KB stages, SW64), 2 CTAs/SM.
// Stage layout: Ahi[8K] Alo[8K] Bhi[8K] Blo[8K].
// EPI=0: fp32 store.  EPI=1: Q-proj (freqs * QSC2 -> bf16 hi/lo Qh/Ql).
// ---------------------------------------------------------------------------
#define GEMM_SMEM (3 * 32768)

template <int EPI>
__global__ __launch_bounds__(256, 2) void gemm_bf16(
    const uint32_t* __restrict__ Ahi, const uint32_t* __restrict__ Alo,
    const uint32_t* __restrict__ Bhi, const uint32_t* __restrict__ Blo,
    float* __restrict__ C, const float* __restrict__ freqs,
    uint32_t* __restrict__ Qh, uint32_t* __restrict__ Ql)
{
    extern __shared__ char sm[];
    const uint32_t smb = smem_to_u32(sm);
    const int tid = threadIdx.x;
    const int wid = tid >> 5;
    const int lane = tid & 31;
    const int wn = wid & 1;          // n half (64)
    const int wm = wid >> 1;         // m quarter (32)
    const int m0 = blockIdx.y * 128;
    const int n0 = blockIdx.x * 128;

    float acc[2][8][4];
#pragma unroll
    for (int i = 0; i < 2; i++)
#pragma unroll
        for (int j = 0; j < 8; j++)
#pragma unroll
            for (int v = 0; v < 4; v++) acc[i][j][v] = 0.0f;

    auto load_stage = [&](int ch, int st) {
        const uint32_t sbase = smb + (uint32_t)st * 32768u;
        const int kc2 = ch * 16;
#pragma unroll
        for (int t = tid; t < 2048; t += 256) {
            const int plane = t >> 9;            // Ahi Alo Bhi Blo
            const int i = t & 511;
            const int row = i >> 2, ck = i & 3;
            const uint32_t dst = sbase + plane * 8192u + SWZ64(row * 64 + ck * 16);
            const uint32_t* bp = (plane == 0) ? Ahi : (plane == 1) ? Alo
                                : (plane == 2) ? Bhi : Blo;
            const int r0 = (plane < 2) ? m0 : n0;
            cp16(dst, bp + (size_t)(r0 + row) * 2048 + kc2 + ck * 4);
        }
    };

    const int q = lane >> 3;
    const int wi = lane & 7;
    const int arow_base = wm * 32 + wi + ((q & 1) ? 8 : 0);
    const int akb_off = (q & 2) ? 16 : 0;
    const int brow_base = wn * 64 + wi + ((q & 2) ? 8 : 0);
    const int bkb_off = (q & 1) ? 16 : 0;

    load_stage(0, 0); CP_COMMIT;
    load_stage(1, 1); CP_COMMIT;

    for (int ch = 0; ch < 128; ++ch) {
        if (ch < 127) CP_WAIT(1); else CP_WAIT(0);
        __syncthreads();
        if (ch + 2 < 128) { load_stage(ch + 2, (ch + 2) % 3); CP_COMMIT; }

        const uint32_t sbase = smb + (uint32_t)(ch % 3) * 32768u;
        const uint32_t pAhi = sbase,           pAlo = sbase + 8192u;
        const uint32_t pBhi = sbase + 16384u,  pBlo = sbase + 24576u;

#pragma unroll
        for (int ks = 0; ks < 2; ++ks) {
            const int kb0 = ks * 32;
            uint32_t ah[2][4], al[2][4];
#pragma unroll
            for (int mt = 0; mt < 2; ++mt) {
                const int r = arow_base + mt * 16;
                const uint32_t off = SWZ64(r * 64 + kb0 + akb_off);
                ldsm_x4(ah[mt][0], ah[mt][1], ah[mt][2], ah[mt][3], pAhi + off);
                ldsm_x4(al[mt][0], al[mt][1], al[mt][2], al[mt][3], pAlo + off);
            }
#pragma unroll
            for (int np = 0; np < 4; ++np) {
                const int rn = brow_base + np * 16;
                const uint32_t offb = SWZ64(rn * 64 + kb0 + bkb_off);
                uint32_t bh[4], bl[4];
                ldsm_x4(bh[0], bh[1], bh[2], bh[3], pBhi + offb);
                ldsm_x4(bl[0], bl[1], bl[2], bl[3], pBlo + offb);
#pragma unroll
                for (int mt = 0; mt < 2; ++mt) {
                    mma_bf16(acc[mt][np * 2],     ah[mt], bh[0], bh[1]);
                    mma_bf16(acc[mt][np * 2 + 1], ah[mt], bh[2], bh[3]);
                    mma_bf16(acc[mt][np * 2],     ah[mt], bl[0], bl[1]);
                    mma_bf16(acc[mt][np * 2 + 1], ah[mt], bl[2], bl[3]);
                    mma_bf16(acc[mt][np * 2],     al[mt], bh[0], bh[1]);
                    mma_bf16(acc[mt][np * 2 + 1], al[mt], bh[2], bh[3]);
                }
            }
        }
    }

    // epilogue from registers
    const int rl = lane >> 2;
    const int cl = (lane & 3) * 2;
#pragma unroll
    for (int mt = 0; mt < 2; ++mt) {
#pragma unroll
        for (int nn = 0; nn < 8; ++nn) {
            const int r = m0 + wm * 32 + mt * 16 + rl;
            const int c = n0 + wn * 64 + nn * 8 + cl;
#pragma unroll
            for (int half = 0; half < 2; ++half) {
                const int rr = r + half * 8;
                const float v0 = acc[mt][nn][half * 2];
                const float v1 = acc[mt][nn][half * 2 + 1];
                if (EPI == 0) {
                    *(float2*)&C[(size_t)rr * DMODEL + c] = make_float2(v0, v1);
                } else {
                    const int b = rr >> 11;
                    const int s = rr & (SEQ - 1);
                    const int h = c >> 7;
                    const int d = c & (HEADD - 1);
                    float2 f = *(const float2*)&freqs[(size_t)s * 64 + (d & 63)];
                    uint32_t hi, lo;
                    pack_hilo(v0 * f.x * QSC2, v1 * f.y * QSC2, hi, lo);
                    const size_t idx = (((size_t)b * NHEADS + h) * SEQ + s) * 64 + (d >> 1);
                    Qh[idx] = hi; Ql[idx] = lo;
                }
            }
        }
    }
}

// ---------------------------------------------------------------------------
// Tensor-core flash attention (causal), bf16 hi/lo 3-pass, base-2 softmax.
// CTA: 64 q-rows x one (b,h), 4 warps x 16 rows, KV blocks of 32.
// 3-stage cp.async (32KB stages), Q staged through region 0, 2 CTAs/SM.
// ---------------------------------------------------------------------------
#define ATT_SMEM (3 * 32768)

__global__ __launch_bounds__(128, 2) void attn_tc(
    const uint32_t* __restrict__ Qhi, const uint32_t* __restrict__ Qlo,
    const uint32_t* __restrict__ Khi, const uint32_t* __restrict__ Klo,
    const uint32_t* __restrict__ Vhi, const uint32_t* __restrict__ Vlo,
    uint32_t* __restrict__ Ohi, uint32_t* __restrict__ Olo)
{
    extern __shared__ char sm[];
    const uint32_t smb = smem_to_u32(sm);
    const int tid = threadIdx.x;
    const int w = tid >> 5;
    const int lane = tid & 31;
    const int bx = gridDim.x - 1 - blockIdx.x;   // big tiles first
    const int by = blockIdx.y;
    const int b = by >> 5, h = by & 31, g = h >> 2;
    const int q0 = bx * 64;
    const int nb = 2 * bx + 2;                   // KV blocks of 32 rows

    // --- Q load (64 rows x 2 planes = 32KB) into region 0 ---
    const size_t qbase = (((size_t)b * NHEADS + h) * SEQ + q0) * 64;
#pragma unroll
    for (int t = tid; t < 2048; t += 128) {
        const int plane = t >> 10;
        const int i = t & 1023;
        const int row = i >> 4, ck = i & 15;
        const uint32_t dst = smb + plane * 16384u + SWZ256(row * 256 + ck * 16);
        cp16(dst, (plane ? Qlo : Qhi) + qbase + (size_t)row * 64 + ck * 4);
    }
    CP_COMMIT;

    const size_t kvbase = ((size_t)b * NKVH + g) * KVLEN * 64;
    auto load_kv = [&](int jb, int region) {
        const uint32_t sb = smb + (uint32_t)region * 32768u;
        const int kv0 = jb * 32;
#pragma unroll
        for (int t = tid; t < 2048; t += 128) {
            const int plane = t >> 9;                 // Khi Klo Vhi Vlo
            const int i = t & 511;
            const int row = i >> 4, ck = i & 15;
            const uint32_t dst = sb + plane * 8192u + SWZ256(row * 256 + ck * 16);
            const uint32_t* base = (plane < 2) ? (plane & 1 ? Klo : Khi)
                                               : (plane & 1 ? Vlo : Vhi);
            cp16(dst, base + kvbase + (size_t)(kv0 + row) * 64 + ck * 4);
        }
    };

    load_kv(0, 1); CP_COMMIT;
    load_kv(1, 2); CP_COMMIT;
    CP_WAIT(2);                 // Q done
    __syncthreads();

    // --- preload Q fragments from region 0 (then region 0 becomes a stage) ---
    const int wi = lane & 7, qq = lane >> 3;
    const int arow = w * 16 + wi + ((qq & 1) ? 8 : 0);
    const int akoff = (qq & 2) ? 16 : 0;
    uint32_t qh[8][4], ql[8][4];
#pragma unroll
    for (int ks = 0; ks < 8; ks++) {
        const uint32_t off = SWZ256(arow * 256 + ks * 32 + akoff);
        ldsm_x4(qh[ks][0], qh[ks][1], qh[ks][2], qh[ks][3], smb + off);
        ldsm_x4(ql[ks][0], ql[ks][1], ql[ks][2], ql[ks][3], smb + 16384u + off);
    }
    __syncthreads();            // all warps done with region 0 before refill

    float oacc[16][4];
#pragma unroll
    for (int i = 0; i < 16; i++)
#pragma unroll
        for (int v = 0; v < 4; v++) oacc[i][v] = 0.0f;
    float mprev0 = -INFINITY, mprev1 = -INFINITY;
    float lsum0 = 0.0f, lsum1 = 0.0f;

    const int rl = lane >> 2, cl2 = (lane & 3) * 2;
    const int row0g = q0 + w * 16 + rl;
    const int row1g = row0g + 8;
    const int brow = wi + ((qq & 2) ? 8 : 0);
    const int bkoff = (qq & 1) ? 16 : 0;
    const int vkr = (lane & 7) + ((lane & 8) ? 8 : 0);
    const int vnoff = (lane & 16) ? 16 : 0;

    for (int jb = 0; jb < nb; ++jb) {
        if (jb < nb - 1) CP_WAIT(1); else CP_WAIT(0);
        __syncthreads();
        if (jb + 2 < nb) { load_kv(jb + 2, jb % 3); CP_COMMIT; }
        const uint32_t sb = smb + (uint32_t)((jb + 1) % 3) * 32768u;

        // --- S = Q @ K^T (3-pass), scores in log2 domain ---
        float sacc[4][4];
#pragma unroll
        for (int i = 0; i < 4; i++)
#pragma unroll
            for (int v = 0; v < 4; v++) sacc[i][v] = 0.0f;
#pragma unroll
        for (int ks = 0; ks < 8; ks++) {
#pragma unroll
            for (int nt2 = 0; nt2 < 2; nt2++) {
                const uint32_t off = SWZ256((nt2 * 16 + brow) * 256 + ks * 32 + bkoff);
                uint32_t bh[4], bl[4];
                ldsm_x4(bh[0], bh[1], bh[2], bh[3], sb + off);
                ldsm_x4(bl[0], bl[1], bl[2], bl[3], sb + 8192u + off);
                mma_bf16(sacc[nt2 * 2],     qh[ks], bh[0], bh[1]);
                mma_bf16(sacc[nt2 * 2 + 1], qh[ks], bh[2], bh[3]);
                mma_bf16(sacc[nt2 * 2],     qh[ks], bl[0], bl[1]);
                mma_bf16(sacc[nt2 * 2 + 1], qh[ks], bl[2], bl[3]);
                mma_bf16(sacc[nt2 * 2],     ql[ks], bh[0], bh[1]);
                mma_bf16(sacc[nt2 * 2 + 1], ql[ks], bh[2], bh[3]);
            }
        }

        // --- causal mask ---
        if (jb >= 2 * bx) {
            const int kv0 = jb * 32;
#pragma unroll
            for (int nt = 0; nt < 4; nt++) {
                const int c0 = kv0 + nt * 8 + cl2;
                const int c1 = c0 + 1;
                if (c0 > row0g) sacc[nt][0] = -1e30f;
                if (c1 > row0g) sacc[nt][1] = -1e30f;
                if (c0 > row1g) sacc[nt][2] = -1e30f;
                if (c1 > row1g) sacc[nt][3] = -1e30f;
            }
        }

        // --- online softmax (base 2) ---
        float mx0 = -1e30f, mx1 = -1e30f;
#pragma unroll
        for (int nt = 0; nt < 4; nt++) {
            mx0 = fmaxf(mx0, fmaxf(sacc[nt][0], sacc[nt][1]));
            mx1 = fmaxf(mx1, fmaxf(sacc[nt][2], sacc[nt][3]));
        }
        mx0 = fmaxf(mx0, __shfl_xor_sync(0xffffffffu, mx0, 1));
        mx0 = fmaxf(mx0, __shfl_xor_sync(0xffffffffu, mx0, 2));
        mx1 = fmaxf(mx1, __shfl_xor_sync(0xffffffffu, mx1, 1));
        mx1 = fmaxf(mx1, __shfl_xor_sync(0xffffffffu, mx1, 2));
        const float mnew0 = fmaxf(mprev0, mx0);
        const float mnew1 = fmaxf(mprev1, mx1);
        const float alpha0 = exp2f(mprev0 - mnew0);
        const float alpha1 = exp2f(mprev1 - mnew1);
        float rs0 = 0.0f, rs1 = 0.0f;
#pragma unroll
        for (int nt = 0; nt < 4; nt++) {
            sacc[nt][0] = exp2f(sacc[nt][0] - mnew0);
            sacc[nt][1] = exp2f(sacc[nt][1] - mnew0);
            sacc[nt][2] = exp2f(sacc[nt][2] - mnew1);
            sacc[nt][3] = exp2f(sacc[nt][3] - mnew1);
            rs0 += sacc[nt][0] + sacc[nt][1];
            rs1 += sacc[nt][2] + sacc[nt][3];
        }
        rs0 += __shfl_xor_sync(0xffffffffu, rs0, 1);
        rs0 += __shfl_xor_sync(0xffffffffu, rs0, 2);
        rs1 += __shfl_xor_sync(0xffffffffu, rs1, 1);
        rs1 += __shfl_xor_sync(0xffffffffu, rs1, 2);
        lsum0 = lsum0 * alpha0 + rs0;
        lsum1 = lsum1 * alpha1 + rs1;
#pragma unroll
        for (int nt = 0; nt < 16; nt++) {
            oacc[nt][0] *= alpha0; oacc[nt][1] *= alpha0;
            oacc[nt][2] *= alpha1; oacc[nt][3] *= alpha1;
        }
        mprev0 = mnew0; mprev1 = mnew1;

        // --- O += P @ V (3-pass); P tiles: jp=0 -> sacc[0,1], jp=1 -> sacc[2,3] ---
#pragma unroll
        for (int jp = 0; jp < 2; jp++) {
            uint32_t pah[4], pal[4];
            pack_hilo(sacc[2 * jp][0],     sacc[2 * jp][1],     pah[0], pal[0]);
            pack_hilo(sacc[2 * jp][2],     sacc[2 * jp][3],     pah[1], pal[1]);
            pack_hilo(sacc[2 * jp + 1][0], sacc[2 * jp + 1][1], pah[2], pal[2]);
            pack_hilo(sacc[2 * jp + 1][2], sacc[2 * jp + 1][3], pah[3], pal[3]);
#pragma unroll
            for (int nt2 = 0; nt2 < 8; nt2++) {
                const uint32_t off = SWZ256((jp * 16 + vkr) * 256 + nt2 * 32 + vnoff);
                uint32_t vh[4], vl[4];
                ldsm_x4_t(vh[0], vh[1], vh[2], vh[3], sb + 16384u + off);
                ldsm_x4_t(vl[0], vl[1], vl[2], vl[3], sb + 24576u + off);
                mma_bf16(oacc[nt2 * 2],     pah, vh[0], vh[1]);
                mma_bf16(oacc[nt2 * 2 + 1], pah, vh[2], vh[3]);
                mma_bf16(oacc[nt2 * 2],     pal, vh[0], vh[1]);
                mma_bf16(oacc[nt2 * 2 + 1], pal, vh[2], vh[3]);
                mma_bf16(oacc[nt2 * 2],     pah, vl[0], vl[1]);
                mma_bf16(oacc[nt2 * 2 + 1], pah, vl[2], vl[3]);
            }
        }
    }

    // --- epilogue ---
    const float inv0 = 1.0f / lsum0;
    const float inv1 = 1.0f / lsum1;
    const size_t r0 = ((size_t)b * SEQ + row0g) * 2048 + h * 64;
    const size_t r1 = ((size_t)b * SEQ + row1g) * 2048 + h * 64;
#pragma unroll
    for (int nt = 0; nt < 16; nt++) {
        const int d2 = (nt * 8 + cl2) >> 1;
        uint32_t hi0, lo0, hi1, lo1;
        pack_hilo(oacc[nt][0] * inv0, oacc[nt][1] * inv0, hi0, lo0);
        pack_hilo(oacc[nt][2] * inv1, oacc[nt][3] * inv1, hi1, lo1);
        Ohi[r0 + d2] = hi0; Olo[r0 + d2] = lo0;
        Ohi[r1 + d2] = hi1; Olo[r1 + d2] = lo1;
    }
}

// ---------------------------------------------------------------------------
extern "C" void kernel_launch(void* const* d_in, const int* in_sizes, int n_in,
                              void* d_out, int out_size)
{
    (void)in_sizes; (void)n_in; (void)out_size;
    const float* x     = (const float*)d_in[0];
    const float* freqs = (const float*)d_in[1];
    const float* wq    = (const float*)d_in[3];
    const float* wo    = (const float*)d_in[6];
    const float* ck    = (const float*)d_in[7];
    const float* cv    = (const float*)d_in[8];
    float* out = (float*)d_out;

    void *xhi, *xlo, *wqhi, *wqlo, *wohi, *wolo, *qhi, *qlo, *ahi, *alo;
    void *khi, *klo, *vhi, *vlo;
    cudaGetSymbolAddress(&xhi, g_xhi);   cudaGetSymbolAddress(&xlo, g_xlo);
    cudaGetSymbolAddress(&wqhi, g_wqhi); cudaGetSymbolAddress(&wqlo, g_wqlo);
    cudaGetSymbolAddress(&wohi, g_wohi); cudaGetSymbolAddress(&wolo, g_wolo);
    cudaGetSymbolAddress(&qhi, g_qhi);   cudaGetSymbolAddress(&qlo, g_qlo);
    cudaGetSymbolAddress(&ahi, g_ahi);   cudaGetSymbolAddress(&alo, g_alo);
    cudaGetSymbolAddress(&khi, g_khi);   cudaGetSymbolAddress(&klo, g_klo);
    cudaGetSymbolAddress(&vhi, g_vhi);   cudaGetSymbolAddress(&vlo, g_vlo);

    cudaFuncSetAttribute(gemm_bf16<0>, cudaFuncAttributeMaxDynamicSharedMemorySize, GEMM_SMEM);
    cudaFuncSetAttribute(gemm_bf16<1>, cudaFuncAttributeMaxDynamicSharedMemorySize, GEMM_SMEM);
    cudaFuncSetAttribute(attn_tc, cudaFuncAttributeMaxDynamicSharedMemorySize, ATT_SMEM);

    dim3 blk(256);
    conv3<<<dim3(2048, 3), blk>>>(
        (const float4*)x, (const float4*)wq, (const float4*)wo,
        (uint2*)xhi, (uint2*)xlo, (uint2*)wqhi, (uint2*)wqlo,
        (uint2*)wohi, (uint2*)wolo);
    conv_kv4<<<dim3(1024, 2), blk>>>(
        (const float4*)ck, (const float4*)cv,
        (uint2*)khi, (uint2*)klo, (uint2*)vhi, (uint2*)vlo);

    gemm_bf16<1><<<dim3(32, 32), blk, GEMM_SMEM>>>(
        (const uint32_t*)xhi, (const uint32_t*)xlo,
        (const uint32_t*)wqhi, (const uint32_t*)wqlo,
        nullptr, freqs, (uint32_t*)qhi, (uint32_t*)qlo);

    attn_tc<<<dim3(32, 64), dim3(128), ATT_SMEM>>>(
        (const uint32_t*)qhi, (const uint32_t*)qlo,
        (const uint32_t*)khi, (const uint32_t*)klo,
        (const uint32_t*)vhi, (const uint32_t*)vlo,
        (uint32_t*)ahi, (uint32_t*)alo);

    gemm_bf16<0><<<dim3(32, 32), blk, GEMM_SMEM>>>(
        (const uint32_t*)ahi, (const uint32_t*)alo,
        (const uint32_t*)wohi, (const uint32_t*)wolo,
        out, nullptr, nullptr, nullptr);
}